// round 1
// baseline (speedup 1.0000x reference)
#include <cuda_runtime.h>
#include <cuda_bf16.h>
#include <stdint.h>

#define TT   8192      // tokens = B*S
#define DD   2048      // hidden dim
#define FF   8192      // ffn dim
#define NE   2         // experts
#define PADT 8448      // 66*128 padded rows
#define MAXT 66        // max 128-row tiles across both experts
#define GEMM_SMEM (3*65536)   // 3 stages * (Ahi+Alo+Bhi+Blo tiles of 16KB)

// ---------------- scratch (device globals; no allocation allowed) ----------------
__device__ __align__(256) __nv_bfloat16 g_Xhi[(size_t)PADT*DD];
__device__ __align__(256) __nv_bfloat16 g_Xlo[(size_t)PADT*DD];
__device__ __align__(256) __nv_bfloat16 g_Wghi[(size_t)NE*FF*DD];
__device__ __align__(256) __nv_bfloat16 g_Wglo[(size_t)NE*FF*DD];
__device__ __align__(256) __nv_bfloat16 g_Wuhi[(size_t)NE*FF*DD];
__device__ __align__(256) __nv_bfloat16 g_Wulo[(size_t)NE*FF*DD];
__device__ __align__(256) __nv_bfloat16 g_Wdhi[(size_t)NE*DD*FF];
__device__ __align__(256) __nv_bfloat16 g_Wdlo[(size_t)NE*DD*FF];
__device__ __align__(256) float g_G[(size_t)PADT*FF];
__device__ __align__(256) float g_U[(size_t)PADT*FF];
__device__ __align__(256) __nv_bfloat16 g_Hhi[(size_t)PADT*FF];
__device__ __align__(256) __nv_bfloat16 g_Hlo[(size_t)PADT*FF];
__device__ int   g_sel[TT];
__device__ float g_topw[TT];
__device__ int   g_tok[PADT];
__device__ int   g_cnt[2];
__device__ int   g_pos[2];

// ---------------- helpers ----------------
__device__ __forceinline__ void split_store4(float4 v, __nv_bfloat16* hi, __nv_bfloat16* lo) {
    float f[4] = {v.x, v.y, v.z, v.w};
    __nv_bfloat16 h[4], l[4];
#pragma unroll
    for (int i = 0; i < 4; ++i) {
        h[i] = __float2bfloat16(f[i]);
        l[i] = __float2bfloat16(f[i] - __bfloat162float(h[i]));
    }
    *(uint2*)hi = *(uint2*)h;
    *(uint2*)lo = *(uint2*)l;
}

__device__ __forceinline__ void cp16(uint32_t saddr, const void* gaddr) {
    asm volatile("cp.async.cg.shared.global [%0], [%1], 16;\n"
                 :: "r"(saddr), "l"(gaddr) : "memory");
}

__device__ __forceinline__ void ldsm4(uint32_t* r, uint32_t addr) {
    asm volatile("ldmatrix.sync.aligned.m8n8.x4.shared.b16 {%0,%1,%2,%3}, [%4];\n"
                 : "=r"(r[0]), "=r"(r[1]), "=r"(r[2]), "=r"(r[3])
                 : "r"(addr) : "memory");
}

__device__ __forceinline__ void mma_bf16(float* c, const uint32_t* a, const uint32_t* b) {
    asm volatile("mma.sync.aligned.m16n8k16.row.col.f32.bf16.bf16.f32 "
                 "{%0,%1,%2,%3}, {%4,%5,%6,%7}, {%8,%9}, {%0,%1,%2,%3};\n"
                 : "+f"(c[0]), "+f"(c[1]), "+f"(c[2]), "+f"(c[3])
                 : "r"(a[0]), "r"(a[1]), "r"(a[2]), "r"(a[3]),
                   "r"(b[0]), "r"(b[1]));
}

// ---------------- small kernels ----------------
__global__ void init_kernel() {
    int i = blockIdx.x * blockDim.x + threadIdx.x;
    if (i < PADT) g_tok[i] = -1;
    if (i == 0) { g_cnt[0] = 0; g_cnt[1] = 0; g_pos[0] = 0; g_pos[1] = 0; }
}

__global__ void router_kernel(const float* __restrict__ x, const float* __restrict__ gw) {
    int gt = blockIdx.x * blockDim.x + threadIdx.x;
    int t = gt >> 5;
    int lane = gt & 31;
    if (t >= TT) return;
    const float* xr = x + (size_t)t * DD;
    float a0 = 0.f, a1 = 0.f;
    for (int d = lane; d < DD; d += 32) {
        float xv = xr[d];
        a0 += xv * gw[d];
        a1 += xv * gw[DD + d];
    }
#pragma unroll
    for (int o = 16; o; o >>= 1) {
        a0 += __shfl_xor_sync(0xffffffffu, a0, o);
        a1 += __shfl_xor_sync(0xffffffffu, a1, o);
    }
    if (lane == 0) {
        int sel = (a0 >= a1) ? 0 : 1;                 // first-max tie-break like argmax
        float m = fmaxf(a0, a1);
        float e0 = expf(a0 - m), e1 = expf(a1 - m);
        float p = ((sel == 0) ? e0 : e1) / (e0 + e1);
        g_sel[t] = sel;
        g_topw[t] = p;
        atomicAdd(&g_cnt[sel], 1);
    }
}

__global__ void assign_kernel() {
    int t = blockIdx.x * blockDim.x + threadIdx.x;
    if (t >= TT) return;
    int sel = g_sel[t];
    int base = sel ? (((g_cnt[0] + 127) >> 7) << 7) : 0;
    int p = atomicAdd(&g_pos[sel], 1);
    g_tok[base + p] = t;
}

__global__ void gatherx_kernel(const float* __restrict__ x) {
    size_t idx = (size_t)blockIdx.x * blockDim.x + threadIdx.x;
    if (idx >= (size_t)PADT * (DD / 4)) return;
    int r = (int)(idx >> 9);        // DD/4 = 512
    int c = (int)(idx & 511);
    int tok = g_tok[r];
    float4 v = make_float4(0.f, 0.f, 0.f, 0.f);
    if (tok >= 0) v = ((const float4*)x)[(size_t)tok * (DD / 4) + c];
    size_t off = (size_t)r * DD + (size_t)c * 4;
    split_store4(v, g_Xhi + off, g_Xlo + off);
}

__global__ void wconv_kernel(const float* __restrict__ w, int which) {
    size_t idx = (size_t)blockIdx.x * blockDim.x + threadIdx.x;
    size_t n4 = (size_t)NE * FF * DD / 4;
    if (idx >= n4) return;
    __nv_bfloat16 *hi, *lo;
    if (which == 0)      { hi = g_Wghi; lo = g_Wglo; }
    else if (which == 1) { hi = g_Wuhi; lo = g_Wulo; }
    else                 { hi = g_Wdhi; lo = g_Wdlo; }
    float4 v = ((const float4*)w)[idx];
    split_store4(v, hi + idx * 4, lo + idx * 4);
}

__global__ void hsplit_kernel() {
    int n0t = (g_cnt[0] + 127) >> 7, n1t = (g_cnt[1] + 127) >> 7;
    size_t n4 = (size_t)(n0t + n1t) * 128 * (FF / 4);
    size_t idx = (size_t)blockIdx.x * blockDim.x + threadIdx.x;
    if (idx >= n4) return;
    float4 g = *(const float4*)(g_G + idx * 4);
    float4 u = *(const float4*)(g_U + idx * 4);
    float4 h;
    h.x = g.x * u.x / (1.f + expf(-g.x));
    h.y = g.y * u.y / (1.f + expf(-g.y));
    h.z = g.z * u.z / (1.f + expf(-g.z));
    h.w = g.w * u.w / (1.f + expf(-g.w));
    split_store4(h, g_Hhi + idx * 4, g_Hlo + idx * 4);
}

// ---------------- GEMM: C[128 rows x 128 cols] per CTA, bf16 hi/lo split ----------------
// SMEM per stage: Ahi(16K) Alo(16K) Bhi(16K) Blo(16K); 128 rows x 64 halves (128B, SW-style xor swizzle)
__device__ __forceinline__ void gemm_load_stage(
    uint32_t sb, int tid, int k0,
    const __nv_bfloat16* Ahi, const __nv_bfloat16* Alo,
    const __nv_bfloat16* Bh,  const __nv_bfloat16* Bl,
    int row0, int col0, int K)
{
#pragma unroll
    for (int i = 0; i < 16; ++i) {
        int q = tid + (i << 8);              // 4096 16B chunks total
        int mat = q >> 10;                   // 0:Ahi 1:Alo 2:Bhi 3:Blo
        int r = (q >> 3) & 127;
        int c = q & 7;
        uint32_t so = sb + (mat << 14) + (r << 7) + (((c ^ (r & 7))) << 4);
        const __nv_bfloat16* base = (mat == 0) ? Ahi : ((mat == 1) ? Alo : ((mat == 2) ? Bh : Bl));
        int gr = (mat < 2) ? (row0 + r) : (col0 + r);
        cp16(so, base + (size_t)gr * K + k0 + (c << 3));
    }
    asm volatile("cp.async.commit_group;\n" ::: "memory");
}

__global__ void __launch_bounds__(256)
moe_gemm_kernel(int which, float* __restrict__ outp)
{
    const __nv_bfloat16 *Ahi, *Alo, *Bh, *Bl;
    float* Cout = nullptr;
    int K, Ntot;
    if (which == 0)      { Ahi = g_Xhi; Alo = g_Xlo; Bh = g_Wghi; Bl = g_Wglo; K = DD; Ntot = FF; Cout = g_G; }
    else if (which == 1) { Ahi = g_Xhi; Alo = g_Xlo; Bh = g_Wuhi; Bl = g_Wulo; K = DD; Ntot = FF; Cout = g_U; }
    else                 { Ahi = g_Hhi; Alo = g_Hlo; Bh = g_Wdhi; Bl = g_Wdlo; K = FF; Ntot = DD; }

    int n0t = (g_cnt[0] + 127) >> 7, n1t = (g_cnt[1] + 127) >> 7;
    int tt = blockIdx.y;
    if (tt >= n0t + n1t) return;
    int expert = (tt < n0t) ? 0 : 1;
    size_t boff = (size_t)expert * Ntot * K;
    Bh += boff; Bl += boff;
    int row0 = tt << 7;
    int col0 = blockIdx.x << 7;

    extern __shared__ char smem[];
    uint32_t sbase = (uint32_t)__cvta_generic_to_shared(smem);
    int tid = threadIdx.x;
    int wid = tid >> 5, lane = tid & 31;
    int wm = wid & 1, wn = wid >> 1;          // warp tile: rows wm*64..+64, cols wn*32..+32

    // lane pieces for ldmatrix addressing
    int lrA = (lane & 7) + (((lane >> 3) & 1) << 3);
    int lcA = lane >> 4;
    int lrB = (lane & 7) + ((lane >> 4) << 3);
    int lcB = (lane >> 3) & 1;

    float acc[4][4][4];
#pragma unroll
    for (int m = 0; m < 4; ++m)
#pragma unroll
        for (int n = 0; n < 4; ++n)
#pragma unroll
            for (int i = 0; i < 4; ++i) acc[m][n][i] = 0.f;

    int kTiles = K >> 6;

    // prologue: 2 stages in flight
    gemm_load_stage(sbase + 0 * 65536, tid, 0,  Ahi, Alo, Bh, Bl, row0, col0, K);
    gemm_load_stage(sbase + 1 * 65536, tid, 64, Ahi, Alo, Bh, Bl, row0, col0, K);

    for (int kt = 0; kt < kTiles; ++kt) {
        asm volatile("cp.async.wait_group 1;\n" ::: "memory");
        __syncthreads();
        int nxt = kt + 2;
        if (nxt < kTiles)
            gemm_load_stage(sbase + (uint32_t)(nxt % 3) * 65536, tid, nxt << 6,
                            Ahi, Alo, Bh, Bl, row0, col0, K);
        uint32_t sb   = sbase + (uint32_t)(kt % 3) * 65536;
        uint32_t sAhi = sb, sAlo = sb + 16384, sBhi = sb + 32768, sBlo = sb + 49152;

#pragma unroll
        for (int k16 = 0; k16 < 4; ++k16) {
            uint32_t ah[4][4], al[4][4];
            uint32_t bh[4][2], bl[4][2];
#pragma unroll
            for (int m = 0; m < 4; ++m) {
                int row = wm * 64 + m * 16 + lrA;
                uint32_t off = ((uint32_t)row << 7) + ((uint32_t)((k16 * 2 + lcA) ^ (row & 7)) << 4);
                ldsm4(ah[m], sAhi + off);
                ldsm4(al[m], sAlo + off);
            }
#pragma unroll
            for (int p = 0; p < 2; ++p) {
                int row = wn * 32 + p * 16 + lrB;
                uint32_t off = ((uint32_t)row << 7) + ((uint32_t)((k16 * 2 + lcB) ^ (row & 7)) << 4);
                uint32_t r4[4];
                ldsm4(r4, sBhi + off);
                bh[2*p][0] = r4[0]; bh[2*p][1] = r4[1]; bh[2*p+1][0] = r4[2]; bh[2*p+1][1] = r4[3];
                ldsm4(r4, sBlo + off);
                bl[2*p][0] = r4[0]; bl[2*p][1] = r4[1]; bl[2*p+1][0] = r4[2]; bl[2*p+1][1] = r4[3];
            }
#pragma unroll
            for (int m = 0; m < 4; ++m)
#pragma unroll
                for (int n = 0; n < 4; ++n) {
                    mma_bf16(acc[m][n], ah[m], bh[n]);   // hi*hi
                    mma_bf16(acc[m][n], ah[m], bl[n]);   // hi*lo
                    mma_bf16(acc[m][n], al[m], bh[n]);   // lo*hi
                }
        }
    }

    // epilogue
    if (which != 2) {
#pragma unroll
        for (int m = 0; m < 4; ++m) {
            int grow = row0 + wm * 64 + m * 16 + (lane >> 2);
#pragma unroll
            for (int n = 0; n < 4; ++n) {
                int gcol = col0 + wn * 32 + n * 8 + (lane & 3) * 2;
                float2 v01; v01.x = acc[m][n][0]; v01.y = acc[m][n][1];
                float2 v23; v23.x = acc[m][n][2]; v23.y = acc[m][n][3];
                *(float2*)(Cout + (size_t)grow * Ntot + gcol) = v01;
                *(float2*)(Cout + (size_t)(grow + 8) * Ntot + gcol) = v23;
            }
        }
    } else {
#pragma unroll
        for (int m = 0; m < 4; ++m) {
            int r0g = row0 + wm * 64 + m * 16 + (lane >> 2);
            int tok0 = g_tok[r0g];
            int tok1 = g_tok[r0g + 8];
            float w0 = (tok0 >= 0) ? g_topw[tok0] : 0.f;
            float w1 = (tok1 >= 0) ? g_topw[tok1] : 0.f;
#pragma unroll
            for (int n = 0; n < 4; ++n) {
                int gcol = col0 + wn * 32 + n * 8 + (lane & 3) * 2;
                if (tok0 >= 0) {
                    float2 v; v.x = w0 * acc[m][n][0]; v.y = w0 * acc[m][n][1];
                    *(float2*)(outp + (size_t)tok0 * DD + gcol) = v;
                }
                if (tok1 >= 0) {
                    float2 v; v.x = w1 * acc[m][n][2]; v.y = w1 * acc[m][n][3];
                    *(float2*)(outp + (size_t)tok1 * DD + gcol) = v;
                }
            }
        }
    }
}

// ---------------- launch ----------------
extern "C" void kernel_launch(void* const* d_in, const int* in_sizes, int n_in,
                              void* d_out, int out_size)
{
    const float* x  = (const float*)d_in[0];
    const float* gw = (const float*)d_in[1];
    const float* wg = (const float*)d_in[2];
    const float* wu = (const float*)d_in[3];
    const float* wd = (const float*)d_in[4];
    float* out = (float*)d_out;

    cudaFuncSetAttribute(moe_gemm_kernel,
                         cudaFuncAttributeMaxDynamicSharedMemorySize, GEMM_SMEM);

    init_kernel<<<(PADT + 255) / 256, 256>>>();
    router_kernel<<<(TT * 32) / 256, 256>>>(x, gw);
    assign_kernel<<<(TT + 255) / 256, 256>>>();
    gatherx_kernel<<<(int)(((size_t)PADT * (DD / 4) + 255) / 256), 256>>>(x);

    int wblocks = (int)(((size_t)NE * FF * DD / 4 + 255) / 256);
    wconv_kernel<<<wblocks, 256>>>(wg, 0);
    wconv_kernel<<<wblocks, 256>>>(wu, 1);
    wconv_kernel<<<wblocks, 256>>>(wd, 2);

    moe_gemm_kernel<<<dim3(FF / 128, MAXT), 256, GEMM_SMEM>>>(0, nullptr);  // gate
    moe_gemm_kernel<<<dim3(FF / 128, MAXT), 256, GEMM_SMEM>>>(1, nullptr);  // up

    hsplit_kernel<<<(int)(((size_t)PADT * (FF / 4) + 255) / 256), 256>>>();

    moe_gemm_kernel<<<dim3(DD / 128, MAXT), 256, GEMM_SMEM>>>(2, out);      // down + scatter
}